// round 8
// baseline (speedup 1.0000x reference)
#include <cuda_runtime.h>
#include <cstdint>

#define BB 16
#define NN 16384
#define SS 512
#define NSAMP 16
#define RR2 0.01f
#define NROWS (BB*SS*NSAMP)      // 131072
#define MLP_BLOCKS 512           // NROWS / 256
#define OUT1_OFF (BB*3*SS)       // 24576

// ---------------- scratch (static device globals; no allocation) -------------
__device__ float4 g_xyz4[BB*NN];          // (x,y,z, x^2+y^2+z^2) - sum NO-FMA
__device__ float4 g_ctr[BB*SS];           // centroid (cx,cy,cz, sn) - sn NO-FMA
__device__ int    g_fps[BB*SS];
__device__ int    g_gidx[BB*SS*NSAMP];
__device__ float  g_y1[NROWS*16];
__device__ float  g_y2[NROWS*16];
__device__ float  g_y3[NROWS*32];
__device__ float  g_part1[MLP_BLOCKS*32];
__device__ float  g_part2[MLP_BLOCKS*32];
__device__ float  g_part3[MLP_BLOCKS*64];
__device__ float  g_scale1[16], g_shift1[16];
__device__ float  g_scale2[16], g_shift2[16];
__device__ float  g_scale3[32], g_shift3[32];

// sum of squares with NO FMA contraction: ((x*x + y*y) + z*z), each op rn
__device__ __forceinline__ float sumsq_nofma(float x, float y, float z) {
    return __fadd_rn(__fadd_rn(__fmul_rn(x, x), __fmul_rn(y, y)), __fmul_rn(z, z));
}

// ---------------- K0: build float4 point array ------------------------------
__global__ void k_xyz4(const float* __restrict__ pts) {
    int t = blockIdx.x * blockDim.x + threadIdx.x;
    if (t >= BB*NN) return;
    int b = t / NN, n = t - b*NN;
    const float* P = pts + (size_t)b*6*NN;
    float x = P[n], y = P[NN+n], z = P[2*NN+n];
    g_xyz4[t] = make_float4(x, y, z, sumsq_nofma(x, y, z));
}

// ---------------- K1: farthest point sampling (one block per batch) ---------
__global__ __launch_bounds__(1024) void k_fps(const float* __restrict__ pts) {
    int b = blockIdx.x;
    const float* P = pts + (size_t)b*6*NN;
    int tid = threadIdx.x;

    float px[16], py[16], pz[16], dist[16];
#pragma unroll
    for (int k = 0; k < 16; k++) {
        int n = tid + (k << 10);
        px[k] = P[n]; py[k] = P[NN+n]; pz[k] = P[2*NN+n];
        dist[k] = 1e10f;
    }

    __shared__ unsigned long long s_key[32];
    __shared__ unsigned long long s_res;
    int far = 0;

    for (int t = 0; t < SS; t++) {
        float cx = P[far], cy = P[NN+far], cz = P[2*NN+far];
        if (tid == 0) {
            g_fps[b*SS + t] = far;
            g_ctr[b*SS + t] = make_float4(cx, cy, cz, sumsq_nofma(cx, cy, cz));
        }
        float bv = -1.0f; int bi = 0;
#pragma unroll
        for (int k = 0; k < 16; k++) {
            float dx = px[k]-cx, dy = py[k]-cy, dz = pz[k]-cz;
            float d  = dx*dx + dy*dy + dz*dz;
            float nd = fminf(dist[k], d);
            dist[k] = nd;
            if (nd > bv) { bv = nd; bi = tid + (k << 10); }
        }
        unsigned long long key =
            ((unsigned long long)__float_as_uint(bv) << 32) |
            (unsigned)(0xFFFFFFFFu - (unsigned)bi);
#pragma unroll
        for (int off = 16; off; off >>= 1) {
            unsigned long long o = __shfl_down_sync(0xffffffffu, key, off);
            if (o > key) key = o;
        }
        int wid = tid >> 5;
        if ((tid & 31) == 0) s_key[wid] = key;
        __syncthreads();
        if (wid == 0) {
            unsigned long long k2 = s_key[tid & 31];
#pragma unroll
            for (int off = 16; off; off >>= 1) {
                unsigned long long o = __shfl_down_sync(0xffffffffu, k2, off);
                if (o > k2) k2 = o;
            }
            if (tid == 0) s_res = k2;
        }
        __syncthreads();
        far = (int)(0xFFFFFFFFu - (unsigned)s_res);
    }
}

// ---------------- K2: ball query (one warp per (b,s)) ------------------------
// sq replicates XLA emission exactly:
//   dot  = GEMM fma-chain over c: fma(c2*q2, fma(c1*q1, mul(c0*q0)))
//   sq   = fsub( fadd(s1, s2), fmul(2, dot) )     (no FMA contraction)
__global__ void k_ball() {
    int w    = threadIdx.x >> 5;
    int lane = threadIdx.x & 31;
    int g    = blockIdx.x * 8 + w;           // b*SS + s
    int b    = g >> 9;
    __shared__ int sbuf[8][16];
    if (lane < 16) sbuf[w][lane] = 0;
    __syncwarp();

    float4 c = g_ctr[g];
    const float4* Q = g_xyz4 + (size_t)b*NN;
    int cnt = 0;
    for (int n0 = 0; n0 < NN; n0 += 32) {
        int n = n0 + lane;
        float4 q = Q[n];
        float d0  = __fmul_rn(c.x, q.x);
        float d1  = fmaf(c.y, q.y, d0);
        float dot = fmaf(c.z, q.z, d1);
        float sq  = __fsub_rn(__fadd_rn(c.w, q.w), __fmul_rn(2.0f, dot));
        bool pred = !(sq > RR2);
        unsigned m = __ballot_sync(0xffffffffu, pred);
        int pos = cnt + __popc(m & ((1u << lane) - 1u));
        if (pred && pos < 16) sbuf[w][pos] = n;
        cnt += __popc(m);
        if (cnt >= 16) break;
    }
    __syncwarp();
    int first = sbuf[w][0];
    if (lane < 16) {
        int v = (lane < cnt) ? sbuf[w][lane] : first;
        g_gidx[g*16 + lane] = v;
    }
}

// ------------- deterministic per-block stat reduction ------------------------
template<int NCH>
__device__ __forceinline__ void stat_reduce(float* ls, float* lq, float* part) {
    __shared__ float ss[8][NCH], sq2[8][NCH];
    int wid = threadIdx.x >> 5, lane = threadIdx.x & 31;
#pragma unroll
    for (int c = 0; c < NCH; c++) {
        float v = ls[c], q = lq[c];
#pragma unroll
        for (int off = 16; off; off >>= 1) {
            v += __shfl_down_sync(0xffffffffu, v, off);
            q += __shfl_down_sync(0xffffffffu, q, off);
        }
        if (lane == 0) { ss[wid][c] = v; sq2[wid][c] = q; }
    }
    __syncthreads();
    if (threadIdx.x < NCH) {
        float v = 0.f, q = 0.f;
#pragma unroll
        for (int ww = 0; ww < 8; ww++) { v += ss[ww][threadIdx.x]; q += sq2[ww][threadIdx.x]; }
        part[blockIdx.x*(2*NCH) + threadIdx.x]       = v;
        part[blockIdx.x*(2*NCH) + NCH + threadIdx.x] = q;
    }
}

template<int NCH>
__device__ __forceinline__ void stat_final(const float* part, const float* g,
                                           const float* be, float* scale, float* shift) {
    int c = threadIdx.x;
    if (c >= NCH) return;
    float s = 0.f, q = 0.f;
    for (int i = 0; i < MLP_BLOCKS; i++) {
        s += part[i*2*NCH + c];
        q += part[i*2*NCH + NCH + c];
    }
    float inv  = 1.0f / (float)NROWS;
    float mean = s * inv;
    float var  = q * inv - mean*mean;
    float rstd = rsqrtf(var + 1e-5f);
    float a = g[c] * rstd;
    scale[c] = a;
    shift[c] = be[c] - mean * a;
}

// ---------------- K3: gather + linear1 (fp32) + stats ------------------------
__global__ __launch_bounds__(256) void k_mlp1(const float* __restrict__ pts,
                                              const float* __restrict__ w1,
                                              const float* __restrict__ b1) {
    int row = blockIdx.x * 256 + threadIdx.x;   // < NROWS
    int g = row >> 4;
    int b = g >> 9;
    int gi = g_gidx[row];
    gi = min(gi, NN-1);
    float4 p = g_xyz4[(size_t)b*NN + gi];
    float4 c = g_ctr[g];
    const float* PNr = pts + (size_t)b*6*NN + 3*NN;
    float f[6];
    f[0] = p.x - c.x; f[1] = p.y - c.y; f[2] = p.z - c.z;
    f[3] = PNr[gi]; f[4] = PNr[NN+gi]; f[5] = PNr[2*NN+gi];

    float ls[16], lq[16];
#pragma unroll
    for (int o = 0; o < 16; o++) {
        float y = 0.f;
#pragma unroll
        for (int cc = 0; cc < 6; cc++) y = fmaf(f[cc], w1[o*6 + cc], y);
        y += b1[o];
        g_y1[row*16 + o] = y;
        ls[o] = y; lq[o] = y*y;
    }
    stat_reduce<16>(ls, lq, g_part1);
}

__global__ void k_stats1(const float* g, const float* be) {
    stat_final<16>(g_part1, g, be, g_scale1, g_shift1);
}

// ---------------- K4: bnrelu1 + linear2 (fp32) + stats -----------------------
__global__ __launch_bounds__(256) void k_mlp2(const float* __restrict__ w2,
                                              const float* __restrict__ b2) {
    int row = blockIdx.x * 256 + threadIdx.x;
    float h[16];
    const float* Y = g_y1 + (size_t)row*16;
#pragma unroll
    for (int k = 0; k < 16; k++)
        h[k] = fmaxf(0.f, Y[k]*g_scale1[k] + g_shift1[k]);

    float ls[16], lq[16];
#pragma unroll
    for (int o = 0; o < 16; o++) {
        float y = 0.f;
#pragma unroll
        for (int k = 0; k < 16; k++) y = fmaf(h[k], w2[o*16 + k], y);
        y += b2[o];
        g_y2[row*16 + o] = y;
        ls[o] = y; lq[o] = y*y;
    }
    stat_reduce<16>(ls, lq, g_part2);
}

__global__ void k_stats2(const float* g, const float* be) {
    stat_final<16>(g_part2, g, be, g_scale2, g_shift2);
}

// ---------------- K5: bnrelu2 + linear3 (fp32) + stats -----------------------
__global__ __launch_bounds__(256) void k_mlp3(const float* __restrict__ w3,
                                              const float* __restrict__ b3) {
    int row = blockIdx.x * 256 + threadIdx.x;
    float h[16];
    const float* Y = g_y2 + (size_t)row*16;
#pragma unroll
    for (int k = 0; k < 16; k++)
        h[k] = fmaxf(0.f, Y[k]*g_scale2[k] + g_shift2[k]);

    float ls[32], lq[32];
#pragma unroll
    for (int o = 0; o < 32; o++) {
        float y = 0.f;
#pragma unroll
        for (int k = 0; k < 16; k++) y = fmaf(h[k], w3[o*16 + k], y);
        y += b3[o];
        g_y3[(size_t)row*32 + o] = y;
        ls[o] = y; lq[o] = y*y;
    }
    stat_reduce<32>(ls, lq, g_part3);
}

__global__ void k_stats3(const float* g, const float* be) {
    stat_final<32>(g_part3, g, be, g_scale3, g_shift3);
}

// ---------------- K6: bnrelu3 + max over nsample + transposed store ----------
__global__ void k_max(float* __restrict__ out) {
    int t = blockIdx.x * 256 + threadIdx.x;   // BB*SS*32
    if (t >= BB*SS*32) return;
    int o = t & 31;
    int g = t >> 5;                // b*SS + s
    int b = g >> 9, s = g & 511;
    float a = g_scale3[o], sh = g_shift3[o];
    const float* Y = g_y3 + (size_t)g*16*32 + o;
    float m = 0.0f;                // relu output >= 0
#pragma unroll
    for (int j = 0; j < 16; j++) {
        float h = fmaxf(0.f, Y[j*32]*a + sh);
        m = fmaxf(m, h);
    }
    out[OUT1_OFF + ((b*32 + o) << 9) + s] = m;
}

// ---------------- K7: new_xyz output (B,3,S) ---------------------------------
__global__ void k_out0(float* __restrict__ out) {
    int t = blockIdx.x * 256 + threadIdx.x;   // BB*3*SS
    if (t >= BB*3*SS) return;
    int b = t / (3*SS);
    int r = t - b*3*SS;
    int c = r >> 9, s = r & 511;
    float4 ct = g_ctr[b*SS + s];
    float v = (c == 0) ? ct.x : (c == 1) ? ct.y : ct.z;
    out[t] = v;
}

// ---------------- launcher ---------------------------------------------------
extern "C" void kernel_launch(void* const* d_in, const int* in_sizes, int n_in,
                              void* d_out, int out_size) {
    const float* pts = (const float*)d_in[0];
    const float* w1  = (const float*)d_in[1];
    const float* b1  = (const float*)d_in[2];
    const float* g1  = (const float*)d_in[3];
    const float* be1 = (const float*)d_in[4];
    const float* w2  = (const float*)d_in[5];
    const float* b2  = (const float*)d_in[6];
    const float* g2  = (const float*)d_in[7];
    const float* be2 = (const float*)d_in[8];
    const float* w3  = (const float*)d_in[9];
    const float* b3  = (const float*)d_in[10];
    const float* g3  = (const float*)d_in[11];
    const float* be3 = (const float*)d_in[12];
    float* out = (float*)d_out;

    k_xyz4<<<(BB*NN + 255)/256, 256>>>(pts);
    k_fps<<<BB, 1024>>>(pts);
    k_ball<<<(BB*SS)/8, 256>>>();
    k_mlp1<<<MLP_BLOCKS, 256>>>(pts, w1, b1);
    k_stats1<<<1, 32>>>(g1, be1);
    k_mlp2<<<MLP_BLOCKS, 256>>>(w2, b2);
    k_stats2<<<1, 32>>>(g2, be2);
    k_mlp3<<<MLP_BLOCKS, 256>>>(w3, b3);
    k_stats3<<<1, 32>>>(g3, be3);
    k_max<<<(BB*SS*32 + 255)/256, 256>>>(out);
    k_out0<<<(BB*3*SS + 255)/256, 256>>>(out);
}

// round 9
// speedup vs baseline: 1.2272x; 1.2272x over previous
#include <cuda_runtime.h>
#include <cstdint>

#define BB 16
#define NN 16384
#define SS 512
#define NSAMP 16
#define RR2 0.01f
#define NROWS (BB*SS*NSAMP)      // 131072
#define MLP_BLOCKS 512           // NROWS / 256
#define OUT1_OFF (BB*3*SS)       // 24576

// ---------------- scratch (static device globals; no allocation) -------------
__device__ float4 g_xyz4[BB*NN];          // (x,y,z, x^2+y^2+z^2) - sum NO-FMA
__device__ float4 g_ctr[BB*SS];           // centroid (cx,cy,cz, sn) - sn NO-FMA
__device__ int    g_gidx[BB*SS*NSAMP];
__device__ float  g_y1[NROWS*16];
__device__ float  g_y2[NROWS*16];
__device__ float  g_y3[NROWS*32];
__device__ float  g_part1[MLP_BLOCKS*32];
__device__ float  g_part2[MLP_BLOCKS*32];
__device__ float  g_part3[MLP_BLOCKS*64];
__device__ float  g_scale1[16], g_shift1[16];
__device__ float  g_scale2[16], g_shift2[16];
__device__ float  g_scale3[32], g_shift3[32];

// sum of squares with NO FMA contraction: ((x*x + y*y) + z*z), each op rn
__device__ __forceinline__ float sumsq_nofma(float x, float y, float z) {
    return __fadd_rn(__fadd_rn(__fmul_rn(x, x), __fmul_rn(y, y)), __fmul_rn(z, z));
}

// ---------------- K0: build float4 point array ------------------------------
__global__ void k_xyz4(const float* __restrict__ pts) {
    int t = blockIdx.x * blockDim.x + threadIdx.x;
    if (t >= BB*NN) return;
    int b = t / NN, n = t - b*NN;
    const float* P = pts + (size_t)b*6*NN;
    float x = P[n], y = P[NN+n], z = P[2*NN+n];
    g_xyz4[t] = make_float4(x, y, z, sumsq_nofma(x, y, z));
}

// ---------------- K1: farthest point sampling (one block per batch) ---------
// Lean reduction: value-only 32-bit fmax shfl; index recovered by candidate
// threads only; winner broadcasts centroid from its registers (no gmem read
// on the critical path). Distance expression text kept IDENTICAL to the
// passing version so nvcc's FMA contraction (bit-matching the reference) is
// unchanged.
__global__ __launch_bounds__(1024) void k_fps(const float* __restrict__ pts) {
    int b = blockIdx.x;
    const float* P = pts + (size_t)b*6*NN;
    int tid = threadIdx.x;
    int lane = tid & 31, wid = tid >> 5;

    float px[16], py[16], pz[16], dist[16];
#pragma unroll
    for (int k = 0; k < 16; k++) {
        int n = tid + (k << 10);
        px[k] = P[n]; py[k] = P[NN+n]; pz[k] = P[2*NN+n];
        dist[k] = 1e10f;
    }

    __shared__ float s_w[32];
    __shared__ float s_wv;
    __shared__ int   s_idx;
    __shared__ float4 s_c;

    // slot 0: centroid = point 0 (owned by tid 0, k 0)
    if (tid == 0) {
        s_c = make_float4(px[0], py[0], pz[0], 0.f);
        g_ctr[b*SS] = make_float4(px[0], py[0], pz[0], sumsq_nofma(px[0], py[0], pz[0]));
        s_idx = 0x7fffffff;
    }
    __syncthreads();

    for (int t = 1; t < SS; t++) {
        float cx = s_c.x, cy = s_c.y, cz = s_c.z;
        float tmax = -1.0f;
#pragma unroll
        for (int k = 0; k < 16; k++) {
            float dx = px[k]-cx, dy = py[k]-cy, dz = pz[k]-cz;
            float d  = dx*dx + dy*dy + dz*dz;
            float nd = fminf(dist[k], d);
            dist[k] = nd;
            tmax = fmaxf(tmax, nd);
        }
        float v = tmax;
#pragma unroll
        for (int off = 16; off; off >>= 1)
            v = fmaxf(v, __shfl_xor_sync(0xffffffffu, v, off));
        if (lane == 0) s_w[wid] = v;
        __syncthreads();                       // B1
        if (wid == 0) {
            float u = s_w[lane];
#pragma unroll
            for (int off = 16; off; off >>= 1)
                u = fmaxf(u, __shfl_xor_sync(0xffffffffu, u, off));
            if (lane == 0) s_wv = u;
        }
        __syncthreads();                       // B2
        float wv = s_wv;
        if (tmax == wv) {                      // rare: ~1 thread
            int best = 0x7fffffff;
#pragma unroll
            for (int k = 0; k < 16; k++)
                if (dist[k] == wv) best = min(best, tid + (k << 10));
            atomicMin(&s_idx, best);
        }
        __syncthreads();                       // B3
        int far = s_idx;
        if ((far & 1023) == tid) {             // owner publishes centroid from regs
            int kk = far >> 10;
            float x = 0.f, y = 0.f, z = 0.f;
#pragma unroll
            for (int k = 0; k < 16; k++)
                if (k == kk) { x = px[k]; y = py[k]; z = pz[k]; }
            s_c = make_float4(x, y, z, 0.f);
            g_ctr[b*SS + t] = make_float4(x, y, z, sumsq_nofma(x, y, z));
        }
        __syncthreads();                       // B4
        if (tid == 0) s_idx = 0x7fffffff;      // consumed; next use is after next B2
    }
}

// ---------------- K2: ball query (one warp per 8 groups) ---------------------
// Flipped loop nest: each warp streams the point array ONCE and tests every
// point against 8 group centroids held in registers. 8x less L1/L2 traffic.
// sq arithmetic sequence identical to the passing version.
__global__ __launch_bounds__(256) void k_ball() {
    int w    = threadIdx.x >> 5;
    int lane = threadIdx.x & 31;
    int gbase = blockIdx.x * 64 + w * 8;      // 64 groups per block, same batch
    int b = gbase >> 9;

    __shared__ int sbuf[8][8][16];

    float4 c[8]; int cnt[8];
#pragma unroll
    for (int j = 0; j < 8; j++) { c[j] = g_ctr[gbase + j]; cnt[j] = 0; }

    const float4* __restrict__ Q = g_xyz4 + (size_t)b*NN;
    unsigned lmask = (1u << lane) - 1u;

    float4 q = Q[lane];
    for (int n0 = 0; n0 < NN; n0 += 32) {
        float4 qn = Q[(n0 + 32 + lane) & (NN - 1)];
        int n = n0 + lane;
#pragma unroll
        for (int j = 0; j < 8; j++) {
            float d0  = __fmul_rn(c[j].x, q.x);
            float d1  = fmaf(c[j].y, q.y, d0);
            float dot = fmaf(c[j].z, q.z, d1);
            float sq  = __fsub_rn(__fadd_rn(c[j].w, q.w), __fmul_rn(2.0f, dot));
            bool pred = !(sq > RR2);
            unsigned m = __ballot_sync(0xffffffffu, pred);
            if (m) {
                int pos = cnt[j] + __popc(m & lmask);
                if (pred && pos < 16) sbuf[w][j][pos] = n;
                cnt[j] += __popc(m);
            }
        }
        q = qn;
    }
    __syncwarp();
#pragma unroll
    for (int j = 0; j < 8; j++) {
        int cj = cnt[j];
        int first = sbuf[w][j][0];
        if (lane < 16) {
            int v = (lane < cj) ? sbuf[w][j][lane] : first;
            g_gidx[(gbase + j)*16 + lane] = v;
        }
    }
}

// ------------- deterministic per-block stat reduction ------------------------
template<int NCH>
__device__ __forceinline__ void stat_reduce(float* ls, float* lq, float* part) {
    __shared__ float ss[8][NCH], sq2[8][NCH];
    int wid = threadIdx.x >> 5, lane = threadIdx.x & 31;
#pragma unroll
    for (int c = 0; c < NCH; c++) {
        float v = ls[c], q = lq[c];
#pragma unroll
        for (int off = 16; off; off >>= 1) {
            v += __shfl_down_sync(0xffffffffu, v, off);
            q += __shfl_down_sync(0xffffffffu, q, off);
        }
        if (lane == 0) { ss[wid][c] = v; sq2[wid][c] = q; }
    }
    __syncthreads();
    if (threadIdx.x < NCH) {
        float v = 0.f, q = 0.f;
#pragma unroll
        for (int ww = 0; ww < 8; ww++) { v += ss[ww][threadIdx.x]; q += sq2[ww][threadIdx.x]; }
        part[blockIdx.x*(2*NCH) + threadIdx.x]       = v;
        part[blockIdx.x*(2*NCH) + NCH + threadIdx.x] = q;
    }
}

template<int NCH>
__device__ __forceinline__ void stat_final(const float* part, const float* g,
                                           const float* be, float* scale, float* shift) {
    int c = threadIdx.x;
    if (c >= NCH) return;
    float s = 0.f, q = 0.f;
    for (int i = 0; i < MLP_BLOCKS; i++) {
        s += part[i*2*NCH + c];
        q += part[i*2*NCH + NCH + c];
    }
    float inv  = 1.0f / (float)NROWS;
    float mean = s * inv;
    float var  = q * inv - mean*mean;
    float rstd = rsqrtf(var + 1e-5f);
    float a = g[c] * rstd;
    scale[c] = a;
    shift[c] = be[c] - mean * a;
}

// ---------------- K3: gather + linear1 (fp32) + stats ------------------------
__global__ __launch_bounds__(256) void k_mlp1(const float* __restrict__ pts,
                                              const float* __restrict__ w1,
                                              const float* __restrict__ b1) {
    int row = blockIdx.x * 256 + threadIdx.x;   // < NROWS
    int g = row >> 4;
    int b = g >> 9;
    int gi = g_gidx[row];
    gi = min(gi, NN-1);
    float4 p = g_xyz4[(size_t)b*NN + gi];
    float4 c = g_ctr[g];
    const float* PNr = pts + (size_t)b*6*NN + 3*NN;
    float f[6];
    f[0] = p.x - c.x; f[1] = p.y - c.y; f[2] = p.z - c.z;
    f[3] = PNr[gi]; f[4] = PNr[NN+gi]; f[5] = PNr[2*NN+gi];

    float ls[16], lq[16];
    float4* O4 = (float4*)(g_y1 + (size_t)row*16);
#pragma unroll
    for (int o4 = 0; o4 < 4; o4++) {
        float4 yv;
        float* yp = (float*)&yv;
#pragma unroll
        for (int oo = 0; oo < 4; oo++) {
            int o = o4*4 + oo;
            float y = 0.f;
#pragma unroll
            for (int cc = 0; cc < 6; cc++) y = fmaf(f[cc], w1[o*6 + cc], y);
            y += b1[o];
            yp[oo] = y;
            ls[o] = y; lq[o] = y*y;
        }
        O4[o4] = yv;
    }
    stat_reduce<16>(ls, lq, g_part1);
}

__global__ void k_stats1(const float* g, const float* be) {
    stat_final<16>(g_part1, g, be, g_scale1, g_shift1);
}

// ---------------- K4: bnrelu1 + linear2 (fp32) + stats -----------------------
__global__ __launch_bounds__(256) void k_mlp2(const float* __restrict__ w2,
                                              const float* __restrict__ b2) {
    int row = blockIdx.x * 256 + threadIdx.x;
    float h[16];
    const float4* Y4 = (const float4*)(g_y1 + (size_t)row*16);
#pragma unroll
    for (int k4 = 0; k4 < 4; k4++) {
        float4 yv = Y4[k4];
        const float* yp = (const float*)&yv;
#pragma unroll
        for (int kk = 0; kk < 4; kk++) {
            int k = k4*4 + kk;
            h[k] = fmaxf(0.f, yp[kk]*g_scale1[k] + g_shift1[k]);
        }
    }

    float ls[16], lq[16];
    float4* O4 = (float4*)(g_y2 + (size_t)row*16);
#pragma unroll
    for (int o4 = 0; o4 < 4; o4++) {
        float4 yv;
        float* yp = (float*)&yv;
#pragma unroll
        for (int oo = 0; oo < 4; oo++) {
            int o = o4*4 + oo;
            float y = 0.f;
#pragma unroll
            for (int k = 0; k < 16; k++) y = fmaf(h[k], w2[o*16 + k], y);
            y += b2[o];
            yp[oo] = y;
            ls[o] = y; lq[o] = y*y;
        }
        O4[o4] = yv;
    }
    stat_reduce<16>(ls, lq, g_part2);
}

__global__ void k_stats2(const float* g, const float* be) {
    stat_final<16>(g_part2, g, be, g_scale2, g_shift2);
}

// ---------------- K5: bnrelu2 + linear3 (fp32) + stats -----------------------
__global__ __launch_bounds__(256) void k_mlp3(const float* __restrict__ w3,
                                              const float* __restrict__ b3) {
    int row = blockIdx.x * 256 + threadIdx.x;
    float h[16];
    const float4* Y4 = (const float4*)(g_y2 + (size_t)row*16);
#pragma unroll
    for (int k4 = 0; k4 < 4; k4++) {
        float4 yv = Y4[k4];
        const float* yp = (const float*)&yv;
#pragma unroll
        for (int kk = 0; kk < 4; kk++) {
            int k = k4*4 + kk;
            h[k] = fmaxf(0.f, yp[kk]*g_scale2[k] + g_shift2[k]);
        }
    }

    float ls[32], lq[32];
    float4* O4 = (float4*)(g_y3 + (size_t)row*32);
#pragma unroll
    for (int o4 = 0; o4 < 8; o4++) {
        float4 yv;
        float* yp = (float*)&yv;
#pragma unroll
        for (int oo = 0; oo < 4; oo++) {
            int o = o4*4 + oo;
            float y = 0.f;
#pragma unroll
            for (int k = 0; k < 16; k++) y = fmaf(h[k], w3[o*16 + k], y);
            y += b3[o];
            yp[oo] = y;
            ls[o] = y; lq[o] = y*y;
        }
        O4[o4] = yv;
    }
    stat_reduce<32>(ls, lq, g_part3);
}

__global__ void k_stats3(const float* g, const float* be) {
    stat_final<32>(g_part3, g, be, g_scale3, g_shift3);
}

// ---------------- K6: bnrelu3 + max over nsample + transposed store ----------
__global__ void k_max(float* __restrict__ out) {
    int t = blockIdx.x * 256 + threadIdx.x;   // BB*SS*32
    if (t >= BB*SS*32) return;
    int o = t & 31;
    int g = t >> 5;                // b*SS + s
    int b = g >> 9, s = g & 511;
    float a = g_scale3[o], sh = g_shift3[o];
    const float* Y = g_y3 + (size_t)g*16*32 + o;
    float m = 0.0f;                // relu output >= 0
#pragma unroll
    for (int j = 0; j < 16; j++) {
        float h = fmaxf(0.f, Y[j*32]*a + sh);
        m = fmaxf(m, h);
    }
    out[OUT1_OFF + ((b*32 + o) << 9) + s] = m;
}

// ---------------- K7: new_xyz output (B,3,S) ---------------------------------
__global__ void k_out0(float* __restrict__ out) {
    int t = blockIdx.x * 256 + threadIdx.x;   // BB*3*SS
    if (t >= BB*3*SS) return;
    int b = t / (3*SS);
    int r = t - b*3*SS;
    int c = r >> 9, s = r & 511;
    float4 ct = g_ctr[b*SS + s];
    float v = (c == 0) ? ct.x : (c == 1) ? ct.y : ct.z;
    out[t] = v;
}

// ---------------- launcher ---------------------------------------------------
extern "C" void kernel_launch(void* const* d_in, const int* in_sizes, int n_in,
                              void* d_out, int out_size) {
    const float* pts = (const float*)d_in[0];
    const float* w1  = (const float*)d_in[1];
    const float* b1  = (const float*)d_in[2];
    const float* g1  = (const float*)d_in[3];
    const float* be1 = (const float*)d_in[4];
    const float* w2  = (const float*)d_in[5];
    const float* b2  = (const float*)d_in[6];
    const float* g2  = (const float*)d_in[7];
    const float* be2 = (const float*)d_in[8];
    const float* w3  = (const float*)d_in[9];
    const float* b3  = (const float*)d_in[10];
    const float* g3  = (const float*)d_in[11];
    const float* be3 = (const float*)d_in[12];
    float* out = (float*)d_out;

    k_xyz4<<<(BB*NN + 255)/256, 256>>>(pts);
    k_fps<<<BB, 1024>>>(pts);
    k_ball<<<(BB*SS)/64, 256>>>();
    k_mlp1<<<MLP_BLOCKS, 256>>>(pts, w1, b1);
    k_stats1<<<1, 32>>>(g1, be1);
    k_mlp2<<<MLP_BLOCKS, 256>>>(w2, b2);
    k_stats2<<<1, 32>>>(g2, be2);
    k_mlp3<<<MLP_BLOCKS, 256>>>(w3, b3);
    k_stats3<<<1, 32>>>(g3, be3);
    k_max<<<(BB*SS*32 + 255)/256, 256>>>(out);
    k_out0<<<(BB*3*SS + 255)/256, 256>>>(out);
}